// round 2
// baseline (speedup 1.0000x reference)
#include <cuda_runtime.h>
#include <stdint.h>

#define NSEG 6
#define NC   512
#define NP   16384   // 128*128
#define BINS 16

// ---------------- scratch (__device__ globals, no allocation) ----------------
__device__ uint8_t g_meta[NSEG * NP];          // bits0-3: primary bin, bit4: extra(bin-1), bit5: masked
__device__ float   g_inv [NSEG * BINS];        // 1/denom per (seg,bin)
__device__ float   g_ys  [NSEG * NC * BINS];   // pooled features, [seg][c*16+k]
__device__ float   g_wA  [NSEG * 2048];
__device__ float   g_wB  [NSEG * 512];

// ---------------- kernel 1: mask + prefix scan + bin metadata ----------------
// grid <<<6, 256>>>, each thread owns 64 contiguous positions.
__global__ void k_scan(const int* __restrict__ parsing) {
    const int seg = blockIdx.x;
    const int tid = threadIdx.x;
    const int lane = tid & 31, wid = tid >> 5;
    const int* ps = parsing + seg * 65536;     // [256,256] plane

    const int base_p = tid * 64;
    uint64_t bits = 0;
    #pragma unroll
    for (int j = 0; j < 64; j++) {
        int p = base_p + j;
        int h = p >> 7, w = p & 127;
        // nearest resize 256->128: src = (2h, 2w)
        if (ps[h * 512 + w * 2] != 0) bits |= (1ull << j);
    }
    int cnt = __popcll(bits);

    // block exclusive scan over 256 per-thread counts
    __shared__ int warp_tot[8];
    __shared__ int warp_off[8];
    __shared__ int sL;
    int x = cnt;
    #pragma unroll
    for (int off = 1; off < 32; off <<= 1) {
        int y = __shfl_up_sync(0xffffffffu, x, off);
        if (lane >= off) x += y;
    }
    if (lane == 31) warp_tot[wid] = x;
    __syncthreads();
    if (tid < 8) {
        int s = 0;
        for (int i = 0; i < tid; i++) s += warp_tot[i];
        warp_off[tid] = s;
    }
    __syncthreads();
    int excl = warp_off[wid] + x - cnt;        // exclusive prefix of this thread
    if (tid == 255) sL = excl + cnt;
    __syncthreads();
    const int L = sL;

    if (tid < BINS) {
        int k = tid;
        int start = (k * L) / BINS;
        int end   = ((k + 1) * L + BINS - 1) / BINS;
        int denom = max(end - start, 1);
        g_inv[seg * BINS + k] = 1.0f / (float)denom;
    }

    uint8_t* mout = g_meta + seg * NP;
    int r = excl;
    #pragma unroll 4
    for (int j = 0; j < 64; j++) {
        uint8_t mb = 0;
        if ((bits >> j) & 1ull) {
            int k1 = (16 * (r + 1) - 1) / L;   // L>0 guaranteed whenever any bit set
            if (k1 > 15) k1 = 15;
            mb = (uint8_t)(32u | (unsigned)k1);
            // overlap: r also belongs to bin k1-1 (AdaptiveAvgPool1d ceil-end)
            if (k1 >= 1 && r == (k1 * L) / 16 && (k1 * L) % 16 != 0) mb |= 16u;
            r++;
        }
        mout[base_p + j] = mb;
    }
}

// ---------------- kernel 2: masked adaptive pooling (reads 201 MB of xs) -----
// grid (NC, NSEG), 256 threads. Two-phase: 8 batched float4 loads (MLP=8),
// then the branchy running-bin accumulation on registers.
__global__ void k_pool(const float* __restrict__ xs) {
    const int c = blockIdx.x, seg = blockIdx.y;
    const int tid = threadIdx.x;
    __shared__ float sbins[BINS];
    __shared__ float sinv [BINS];
    if (tid < BINS) {
        sbins[tid] = 0.0f;
        sinv[tid]  = g_inv[seg * BINS + tid];
    }
    __syncthreads();

    const float4* __restrict__ x4 = (const float4*)(xs + ((size_t)seg * NC + c) * NP);
    const uchar4* __restrict__ m4 = (const uchar4*)(g_meta + seg * NP);

    int   cur = -1;
    float acc = 0.0f;
    #pragma unroll
    for (int half = 0; half < 2; half++) {
        float4 xv[8];
        uchar4 mv[8];
        #pragma unroll
        for (int i = 0; i < 8; i++) {
            int idx = (half * 8 + i) * 256 + tid;   // coalesced
            xv[i] = x4[idx];
            mv[i] = m4[idx];
        }
        #pragma unroll
        for (int i = 0; i < 8; i++) {
            float    xa[4] = {xv[i].x, xv[i].y, xv[i].z, xv[i].w};
            unsigned ma[4] = {mv[i].x, mv[i].y, mv[i].z, mv[i].w};
            #pragma unroll
            for (int j = 0; j < 4; j++) {
                unsigned mm = ma[j];
                if (mm & 32u) {
                    int k1 = (int)(mm & 15u);
                    if (k1 != cur) {               // flush on bin change (rank monotone in p)
                        if (cur >= 0) atomicAdd(&sbins[cur], acc * sinv[cur]);
                        cur = k1; acc = 0.0f;
                    }
                    acc += xa[j];
                    if (mm & 16u)                  // rare overlap into previous bin
                        atomicAdd(&sbins[k1 - 1], xa[j] * sinv[k1 - 1]);
                }
            }
        }
    }
    if (cur >= 0) atomicAdd(&sbins[cur], acc * sinv[cur]);
    __syncthreads();
    if (tid < BINS)
        g_ys[((size_t)seg * NC + c) * BINS + tid] = sbins[tid];
}

// ---------------- generic GEMV: warp per row, batched float4 loads -----------
// 128-thread blocks (4 warps) for fine wave balance; 8 W-loads in flight/lane.
template <int NDIM>
__global__ void k_gemv(const float* __restrict__ W, const float* __restrict__ xin,
                       const float* __restrict__ b, float* __restrict__ y,
                       int rows_per_seg, int x_seg_stride, int y_seg_stride) {
    const int gwarp = (blockIdx.x * blockDim.x + threadIdx.x) >> 5;
    const int lane  = threadIdx.x & 31;
    const int row   = gwarp;
    const int seg   = row / rows_per_seg;
    const int m     = row - seg * rows_per_seg;

    const float4* __restrict__ W4 = (const float4*)(W + (size_t)row * NDIM);
    const float4* __restrict__ x4 = (const float4*)(xin + (size_t)seg * x_seg_stride);

    constexpr int ITERS = NDIM / 128;               // float4 steps per lane
    constexpr int UN    = (ITERS >= 8) ? 8 : ITERS; // batch depth

    float acc0 = 0.0f, acc1 = 0.0f;
    #pragma unroll
    for (int ii = 0; ii < ITERS; ii += UN) {
        float4 w[UN];
        #pragma unroll
        for (int j = 0; j < UN; j++)
            w[j] = W4[(ii + j) * 32 + lane];
        #pragma unroll
        for (int j = 0; j < UN; j++) {
            float4 v = x4[(ii + j) * 32 + lane];
            if (j & 1) acc1 += w[j].x * v.x + w[j].y * v.y + w[j].z * v.z + w[j].w * v.w;
            else       acc0 += w[j].x * v.x + w[j].y * v.y + w[j].z * v.z + w[j].w * v.w;
        }
    }
    float acc = acc0 + acc1;
    #pragma unroll
    for (int off = 16; off; off >>= 1) acc += __shfl_down_sync(0xffffffffu, acc, off);
    if (lane == 0) y[(size_t)seg * y_seg_stride + m] = acc + b[row];
}

// ---------------- final cascade: p1/p2/p3 on w0, per-segment block ----------
__global__ void k_final(const float* __restrict__ p1w, const float* __restrict__ p1b,
                        const float* __restrict__ p2w, const float* __restrict__ p2b,
                        const float* __restrict__ p3w, const float* __restrict__ p3b,
                        float* __restrict__ out) {
    const int seg = blockIdx.x;
    const int tid = threadIdx.x, lane = tid & 31, wid = tid >> 5; // 8 warps
    __shared__ float w0s[512], w1s[256], w2s[128];
    float* o = out + seg * 960;

    for (int i = tid; i < 512; i += 256) w0s[i] = o[i];   // w0 written by fcC
    __syncthreads();

    for (int m = wid; m < 256; m += 8) {                   // w1 = p1_w @ w0 + p1_b
        float acc = 0.0f;
        for (int n = lane; n < 512; n += 32) acc += p1w[m * 512 + n] * w0s[n];
        #pragma unroll
        for (int off = 16; off; off >>= 1) acc += __shfl_down_sync(0xffffffffu, acc, off);
        if (lane == 0) { float v = acc + p1b[m]; w1s[m] = v; o[512 + m] = v; }
    }
    __syncthreads();

    for (int m = wid; m < 128; m += 8) {                   // w2
        float acc = 0.0f;
        for (int n = lane; n < 256; n += 32) acc += p2w[m * 256 + n] * w1s[n];
        #pragma unroll
        for (int off = 16; off; off >>= 1) acc += __shfl_down_sync(0xffffffffu, acc, off);
        if (lane == 0) { float v = acc + p2b[m]; w2s[m] = v; o[768 + m] = v; }
    }
    __syncthreads();

    for (int m = wid; m < 64; m += 8) {                    // w3
        float acc = 0.0f;
        for (int n = lane; n < 128; n += 32) acc += p3w[m * 128 + n] * w2s[n];
        #pragma unroll
        for (int off = 16; off; off >>= 1) acc += __shfl_down_sync(0xffffffffu, acc, off);
        if (lane == 0) o[896 + m] = acc + p3b[m];
    }
}

// ---------------- launch ----------------------------------------------------
extern "C" void kernel_launch(void* const* d_in, const int* in_sizes, int n_in,
                              void* d_out, int out_size) {
    const float* xs      = (const float*)d_in[0];   // [6,1,512,128,128]
    const int*   parsing = (const int*)  d_in[1];   // [1,6,256,256]
    const float* fcA_w   = (const float*)d_in[2];   // [6,2048,8192]
    const float* fcA_b   = (const float*)d_in[3];   // [6,2048]
    const float* fcB_w   = (const float*)d_in[4];   // [6,512,2048]
    const float* fcB_b   = (const float*)d_in[5];   // [6,512]
    const float* fcC_w   = (const float*)d_in[6];   // [6,512,512]
    const float* fcC_b   = (const float*)d_in[7];   // [6,512]
    const float* p1_w    = (const float*)d_in[8];   // [256,512]
    const float* p1_b    = (const float*)d_in[9];
    const float* p2_w    = (const float*)d_in[10];  // [128,256]
    const float* p2_b    = (const float*)d_in[11];
    const float* p3_w    = (const float*)d_in[12];  // [64,128]
    const float* p3_b    = (const float*)d_in[13];
    float* out = (float*)d_out;                     // [6,1,960]

    float* ysp; cudaGetSymbolAddress((void**)&ysp, g_ys);
    float* wAp; cudaGetSymbolAddress((void**)&wAp, g_wA);
    float* wBp; cudaGetSymbolAddress((void**)&wBp, g_wB);

    // 1) mask + scan + bin metadata
    k_scan<<<NSEG, 256>>>(parsing);

    // 2) masked adaptive pooling over xs (201 MB)
    k_pool<<<dim3(NC, NSEG), 256>>>(xs);

    // 3) fcA: 6x[2048x8192] GEMV (402 MB) -> g_wA    (4 warps/block)
    k_gemv<8192><<<(NSEG * 2048) / 4, 128>>>(fcA_w, ysp, fcA_b, wAp, 2048, NC * BINS, 2048);

    // 4) fcB: 6x[512x2048] -> g_wB
    k_gemv<2048><<<(NSEG * 512) / 4, 128>>>(fcB_w, wAp, fcB_b, wBp, 512, 2048, 512);

    // 5) fcC: 6x[512x512] -> out[seg*960 + 0..511] (w0)
    k_gemv<512><<<(NSEG * 512) / 4, 128>>>(fcC_w, wBp, fcC_b, out, 512, 512, 960);

    // 6) p1/p2/p3 cascade -> out[seg*960 + 512..959]
    k_final<<<NSEG, 256>>>(p1_w, p1_b, p2_w, p2_b, p3_w, p3_b, out);
}

// round 3
// speedup vs baseline: 1.3251x; 1.3251x over previous
#include <cuda_runtime.h>
#include <stdint.h>

#define NSEG 6
#define NC   512
#define NP   16384   // 128*128
#define BINS 16

// ---------------- scratch (__device__ globals, no allocation) ----------------
__device__ uint8_t g_meta[NSEG * NP];          // bits0-3: primary bin, bit4: extra(bin-1), bit5: masked
__device__ float   g_inv [NSEG * BINS];        // 1/denom per (seg,bin)
__device__ float   g_ys  [NSEG * NC * BINS];   // pooled features, [seg][c*16+k]
__device__ float   g_wA  [NSEG * 2048];
__device__ float   g_wB  [NSEG * 512];

// ---------------- dummy: shifts the ncu capture slot onto fcA ---------------
__global__ void k_nop() {}

// ---------------- kernel 1: mask + prefix scan + bin metadata ----------------
__global__ void k_scan(const int* __restrict__ parsing) {
    const int seg = blockIdx.x;
    const int tid = threadIdx.x;
    const int lane = tid & 31, wid = tid >> 5;
    const int* ps = parsing + seg * 65536;     // [256,256] plane

    const int base_p = tid * 64;
    uint64_t bits = 0;
    #pragma unroll
    for (int j = 0; j < 64; j++) {
        int p = base_p + j;
        int h = p >> 7, w = p & 127;
        if (ps[h * 512 + w * 2] != 0) bits |= (1ull << j);   // nearest 256->128: (2h,2w)
    }
    int cnt = __popcll(bits);

    __shared__ int warp_tot[8];
    __shared__ int warp_off[8];
    __shared__ int sL;
    int x = cnt;
    #pragma unroll
    for (int off = 1; off < 32; off <<= 1) {
        int y = __shfl_up_sync(0xffffffffu, x, off);
        if (lane >= off) x += y;
    }
    if (lane == 31) warp_tot[wid] = x;
    __syncthreads();
    if (tid < 8) {
        int s = 0;
        for (int i = 0; i < tid; i++) s += warp_tot[i];
        warp_off[tid] = s;
    }
    __syncthreads();
    int excl = warp_off[wid] + x - cnt;
    if (tid == 255) sL = excl + cnt;
    __syncthreads();
    const int L = sL;

    if (tid < BINS) {
        int k = tid;
        int start = (k * L) / BINS;
        int end   = ((k + 1) * L + BINS - 1) / BINS;
        int denom = max(end - start, 1);
        g_inv[seg * BINS + k] = 1.0f / (float)denom;
    }

    uint8_t* mout = g_meta + seg * NP;
    int r = excl;
    #pragma unroll 4
    for (int j = 0; j < 64; j++) {
        uint8_t mb = 0;
        if ((bits >> j) & 1ull) {
            int k1 = (16 * (r + 1) - 1) / L;
            if (k1 > 15) k1 = 15;
            mb = (uint8_t)(32u | (unsigned)k1);
            if (k1 >= 1 && r == (k1 * L) / 16 && (k1 * L) % 16 != 0) mb |= 16u;
            r++;
        }
        mout[base_p + j] = mb;
    }
}

// ---------------- kernel 2: masked adaptive pooling (R1 form, known-good) ----
__global__ void k_pool(const float* __restrict__ xs) {
    const int c = blockIdx.x, seg = blockIdx.y;
    const int tid = threadIdx.x;
    __shared__ float sbins[BINS];
    __shared__ float sinv [BINS];
    if (tid < BINS) {
        sbins[tid] = 0.0f;
        sinv[tid]  = g_inv[seg * BINS + tid];
    }
    __syncthreads();

    const float4* x4 = (const float4*)(xs + ((size_t)seg * NC + c) * NP);
    const uchar4* m4 = (const uchar4*)(g_meta + seg * NP);

    int   cur = -1;
    float acc = 0.0f;
    #pragma unroll 4
    for (int i = 0; i < 16; i++) {
        int idx = i * 256 + tid;               // coalesced
        float4 xv = x4[idx];
        uchar4 mv = m4[idx];
        float xa[4] = {xv.x, xv.y, xv.z, xv.w};
        unsigned ma[4] = {mv.x, mv.y, mv.z, mv.w};
        #pragma unroll
        for (int j = 0; j < 4; j++) {
            unsigned mm = ma[j];
            if (mm & 32u) {
                int k1 = (int)(mm & 15u);
                if (k1 != cur) {
                    if (cur >= 0) atomicAdd(&sbins[cur], acc * sinv[cur]);
                    cur = k1; acc = 0.0f;
                }
                acc += xa[j];
                if (mm & 16u)
                    atomicAdd(&sbins[k1 - 1], xa[j] * sinv[k1 - 1]);
            }
        }
    }
    if (cur >= 0) atomicAdd(&sbins[cur], acc * sinv[cur]);
    __syncthreads();
    if (tid < BINS)
        g_ys[((size_t)seg * NC + c) * BINS + tid] = sbins[tid];
}

// ---------------- fcA: block-per-row, full load batch up front ---------------
// row = 8192 floats = 32KB; 256 threads x 8 float4 each, all loads issued
// before any consumption (128B in flight per thread). ys reads are L1 hits.
__global__ void k_fcA(const float* __restrict__ W, const float* __restrict__ b) {
    const int row = blockIdx.x;                 // 0..12287
    const int seg = row >> 11;
    const int tid = threadIdx.x;
    const int lane = tid & 31, wid = tid >> 5;

    const float4* __restrict__ W4 = (const float4*)(W + (size_t)row * 8192);
    const float4* __restrict__ x4 = (const float4*)(g_ys + (size_t)seg * 8192);

    float4 w0 = W4[0 * 256 + tid];
    float4 w1 = W4[1 * 256 + tid];
    float4 w2 = W4[2 * 256 + tid];
    float4 w3 = W4[3 * 256 + tid];
    float4 w4 = W4[4 * 256 + tid];
    float4 w5 = W4[5 * 256 + tid];
    float4 w6 = W4[6 * 256 + tid];
    float4 w7 = W4[7 * 256 + tid];

    float acc0 = 0.f, acc1 = 0.f;
    {
        float4 v;
        v = x4[0 * 256 + tid]; acc0 += w0.x*v.x + w0.y*v.y + w0.z*v.z + w0.w*v.w;
        v = x4[1 * 256 + tid]; acc1 += w1.x*v.x + w1.y*v.y + w1.z*v.z + w1.w*v.w;
        v = x4[2 * 256 + tid]; acc0 += w2.x*v.x + w2.y*v.y + w2.z*v.z + w2.w*v.w;
        v = x4[3 * 256 + tid]; acc1 += w3.x*v.x + w3.y*v.y + w3.z*v.z + w3.w*v.w;
        v = x4[4 * 256 + tid]; acc0 += w4.x*v.x + w4.y*v.y + w4.z*v.z + w4.w*v.w;
        v = x4[5 * 256 + tid]; acc1 += w5.x*v.x + w5.y*v.y + w5.z*v.z + w5.w*v.w;
        v = x4[6 * 256 + tid]; acc0 += w6.x*v.x + w6.y*v.y + w6.z*v.z + w6.w*v.w;
        v = x4[7 * 256 + tid]; acc1 += w7.x*v.x + w7.y*v.y + w7.z*v.z + w7.w*v.w;
    }
    float acc = acc0 + acc1;
    #pragma unroll
    for (int off = 16; off; off >>= 1) acc += __shfl_down_sync(0xffffffffu, acc, off);

    __shared__ float ssum[8];
    if (lane == 0) ssum[wid] = acc;
    __syncthreads();
    if (tid == 0) {
        float s = ssum[0] + ssum[1] + ssum[2] + ssum[3]
                + ssum[4] + ssum[5] + ssum[6] + ssum[7];
        g_wA[row] = s + b[row];
    }
}

// ---------------- generic GEMV (R1 form): warp per row, unroll 4 -------------
template <int NDIM>
__global__ void k_gemv(const float* __restrict__ W, const float* __restrict__ xin,
                       const float* __restrict__ b, float* __restrict__ y,
                       int rows_per_seg, int x_seg_stride, int y_seg_stride) {
    const int gwarp = (blockIdx.x * blockDim.x + threadIdx.x) >> 5;
    const int lane  = threadIdx.x & 31;
    const int row   = gwarp;
    const int seg   = row / rows_per_seg;
    const int m     = row - seg * rows_per_seg;

    const float4* W4 = (const float4*)(W + (size_t)row * NDIM);
    const float4* x4 = (const float4*)(xin + (size_t)seg * x_seg_stride);

    float acc = 0.0f;
    #pragma unroll 4
    for (int i = lane; i < NDIM / 4; i += 32) {
        float4 w = W4[i];
        float4 v = x4[i];
        acc += w.x * v.x + w.y * v.y + w.z * v.z + w.w * v.w;
    }
    #pragma unroll
    for (int off = 16; off; off >>= 1) acc += __shfl_down_sync(0xffffffffu, acc, off);
    if (lane == 0) y[(size_t)seg * y_seg_stride + m] = acc + b[row];
}

// ---------------- final cascade ----------------------------------------------
__global__ void k_final(const float* __restrict__ p1w, const float* __restrict__ p1b,
                        const float* __restrict__ p2w, const float* __restrict__ p2b,
                        const float* __restrict__ p3w, const float* __restrict__ p3b,
                        float* __restrict__ out) {
    const int seg = blockIdx.x;
    const int tid = threadIdx.x, lane = tid & 31, wid = tid >> 5; // 8 warps
    __shared__ float w0s[512], w1s[256], w2s[128];
    float* o = out + seg * 960;

    for (int i = tid; i < 512; i += 256) w0s[i] = o[i];
    __syncthreads();

    for (int m = wid; m < 256; m += 8) {
        float acc = 0.0f;
        for (int n = lane; n < 512; n += 32) acc += p1w[m * 512 + n] * w0s[n];
        #pragma unroll
        for (int off = 16; off; off >>= 1) acc += __shfl_down_sync(0xffffffffu, acc, off);
        if (lane == 0) { float v = acc + p1b[m]; w1s[m] = v; o[512 + m] = v; }
    }
    __syncthreads();

    for (int m = wid; m < 128; m += 8) {
        float acc = 0.0f;
        for (int n = lane; n < 256; n += 32) acc += p2w[m * 256 + n] * w1s[n];
        #pragma unroll
        for (int off = 16; off; off >>= 1) acc += __shfl_down_sync(0xffffffffu, acc, off);
        if (lane == 0) { float v = acc + p2b[m]; w2s[m] = v; o[768 + m] = v; }
    }
    __syncthreads();

    for (int m = wid; m < 64; m += 8) {
        float acc = 0.0f;
        for (int n = lane; n < 128; n += 32) acc += p3w[m * 128 + n] * w2s[n];
        #pragma unroll
        for (int off = 16; off; off >>= 1) acc += __shfl_down_sync(0xffffffffu, acc, off);
        if (lane == 0) o[896 + m] = acc + p3b[m];
    }
}

// ---------------- launch ------------------------------------------------------
extern "C" void kernel_launch(void* const* d_in, const int* in_sizes, int n_in,
                              void* d_out, int out_size) {
    const float* xs      = (const float*)d_in[0];
    const int*   parsing = (const int*)  d_in[1];
    const float* fcA_w   = (const float*)d_in[2];
    const float* fcA_b   = (const float*)d_in[3];
    const float* fcB_w   = (const float*)d_in[4];
    const float* fcB_b   = (const float*)d_in[5];
    const float* fcC_w   = (const float*)d_in[6];
    const float* fcC_b   = (const float*)d_in[7];
    const float* p1_w    = (const float*)d_in[8];
    const float* p1_b    = (const float*)d_in[9];
    const float* p2_w    = (const float*)d_in[10];
    const float* p2_b    = (const float*)d_in[11];
    const float* p3_w    = (const float*)d_in[12];
    const float* p3_b    = (const float*)d_in[13];
    float* out = (float*)d_out;                     // [6,1,960]

    float* wAp; cudaGetSymbolAddress((void**)&wAp, g_wA);
    float* wBp; cudaGetSymbolAddress((void**)&wBp, g_wB);

    // 0) nop — shifts the fixed ncu capture slot onto fcA
    k_nop<<<1, 32>>>();

    // 1) mask + scan + bin metadata
    k_scan<<<NSEG, 256>>>(parsing);

    // 2) masked adaptive pooling over xs (201 MB)
    k_pool<<<dim3(NC, NSEG), 256>>>(xs);

    // 3) fcA: block-per-row (402 MB) -> g_wA
    k_fcA<<<NSEG * 2048, 256>>>(fcA_w, fcA_b);

    // 4) fcB: 6x[512x2048] -> g_wB
    k_gemv<2048><<<(NSEG * 512) / 8, 256>>>(fcB_w, wAp, fcB_b, wBp, 512, 2048, 512);

    // 5) fcC: 6x[512x512] -> out[seg*960 + 0..511] (w0)
    k_gemv<512><<<(NSEG * 512) / 8, 256>>>(fcC_w, wBp, fcC_b, out, 512, 512, 960);

    // 6) p1/p2/p3 cascade -> out[seg*960 + 512..959]
    k_final<<<NSEG, 256>>>(p1_w, p1_b, p2_w, p2_b, p3_w, p3_b, out);
}

// round 4
// speedup vs baseline: 2.4390x; 1.8407x over previous
#include <cuda_runtime.h>
#include <stdint.h>

#define NSEG 6
#define NC   512
#define NP   16384   // 128*128
#define BINS 16

// ---------------- scratch (__device__ globals, no allocation) ----------------
__device__ uint32_t g_mbits[NSEG * 512];       // mask bits, word p>>5, bit p&31
__device__ int      g_pb  [NSEG * BINS];       // bin position interval begin (incl)
__device__ int      g_pe  [NSEG * BINS];       // bin position interval end   (incl)
__device__ float    g_inv [NSEG * BINS];       // 1/denom per (seg,bin)
__device__ float    g_ys  [NSEG * NC * BINS];  // pooled features
__device__ float    g_wA  [NSEG * 2048];
__device__ float    g_wB  [NSEG * 512];

// ---------------- dummies: shift the ncu capture slot onto k_pool ------------
__global__ void k_nop() {}

// ---------------- kernel 1: mask bits + scan + bin intervals -----------------
__global__ void k_scan(const int* __restrict__ parsing) {
    const int seg = blockIdx.x;
    const int tid = threadIdx.x;
    const int lane = tid & 31, wid = tid >> 5;
    const int* ps = parsing + seg * 65536;     // [256,256] plane

    const int base_p = tid * 64;
    uint64_t bits = 0;
    #pragma unroll
    for (int j = 0; j < 64; j++) {
        int p = base_p + j;
        int h = p >> 7, w = p & 127;
        if (ps[h * 512 + w * 2] != 0) bits |= (1ull << j);   // nearest 256->128: (2h,2w)
    }
    int cnt = __popcll(bits);

    __shared__ int warp_tot[8];
    __shared__ int warp_off[8];
    __shared__ int sL;
    __shared__ int s_pb[BINS], s_pe[BINS];
    int x = cnt;
    #pragma unroll
    for (int off = 1; off < 32; off <<= 1) {
        int y = __shfl_up_sync(0xffffffffu, x, off);
        if (lane >= off) x += y;
    }
    if (lane == 31) warp_tot[wid] = x;
    if (tid < BINS) { s_pb[tid] = NP; s_pe[tid] = -1; }   // empty-bin defaults
    __syncthreads();
    if (tid < 8) {
        int s = 0;
        for (int i = 0; i < tid; i++) s += warp_tot[i];
        warp_off[tid] = s;
    }
    __syncthreads();
    int excl = warp_off[wid] + x - cnt;
    if (tid == 255) sL = excl + cnt;
    __syncthreads();
    const int L = sL;

    // mask bit words
    g_mbits[seg * 512 + tid * 2 + 0] = (uint32_t)(bits);
    g_mbits[seg * 512 + tid * 2 + 1] = (uint32_t)(bits >> 32);

    // bin boundary positions: rank r is start_k iff floor(kL/16)==r for
    // k=ceil(16r/L); rank r is end_k-1 iff ceil(kp1*L/16)==r+1 for kp1=floor(16(r+1)/L).
    if (L > 0) {
        int r = excl;
        for (int j = 0; j < 64; j++) {
            if ((bits >> j) & 1ull) {
                int p = base_p + j;
                int k = (int)(((long long)16 * r + L - 1) / L);
                if (k < BINS && (int)(((long long)k * L) >> 4) == r) s_pb[k] = p;
                int t = r + 1;
                int kp1 = (int)(((long long)16 * t) / L);
                if (kp1 >= 1 && kp1 <= BINS &&
                    (int)(((long long)kp1 * L + 15) >> 4) == t) s_pe[kp1 - 1] = p;
                r++;
            }
        }
    }
    __syncthreads();

    if (tid < BINS) {
        int k = tid;
        int start = (k * L) / BINS;
        int end   = ((k + 1) * L + BINS - 1) / BINS;
        int denom = max(end - start, 1);
        g_inv[seg * BINS + k] = 1.0f / (float)denom;
        g_pb [seg * BINS + k] = s_pb[k];
        g_pe [seg * BINS + k] = s_pe[k];
    }
}

// ---------------- kernel 2: branch-free masked segment sums ------------------
// grid (NC, NSEG), 256 threads. Per bin k: sum x[p]*mask[p] over the bin's
// contiguous position interval. Coalesced LDG + broadcast LDS + SEL + FFMA.
__global__ void k_pool(const float* __restrict__ xs) {
    const int c = blockIdx.x, seg = blockIdx.y;
    const int tid = threadIdx.x, lane = tid & 31;
    __shared__ uint32_t smb[512];
    __shared__ int   spb[BINS], spe[BINS];
    __shared__ float sinv[BINS];
    __shared__ float sbins[BINS];

    smb[tid]       = g_mbits[seg * 512 + tid];
    smb[tid + 256] = g_mbits[seg * 512 + 256 + tid];
    if (tid < BINS) {
        spb [tid] = g_pb [seg * BINS + tid];
        spe [tid] = g_pe [seg * BINS + tid];
        sinv[tid] = g_inv[seg * BINS + tid];
        sbins[tid] = 0.0f;
    }
    __syncthreads();

    const float* __restrict__ x = xs + ((size_t)seg * NC + c) * NP;

    float accs[BINS];
    #pragma unroll
    for (int k = 0; k < BINS; k++) {
        float acc = 0.0f;
        const int e = spe[k];
        for (int p = spb[k] + tid; p <= e; p += 256) {
            float m = ((smb[p >> 5] >> (p & 31)) & 1u) ? 1.0f : 0.0f;
            acc += x[p] * m;
        }
        accs[k] = acc;
    }

    #pragma unroll
    for (int k = 0; k < BINS; k++) {
        float acc = accs[k];
        #pragma unroll
        for (int off = 16; off; off >>= 1) acc += __shfl_down_sync(0xffffffffu, acc, off);
        if (lane == 0) atomicAdd(&sbins[k], acc);
    }
    __syncthreads();
    if (tid < BINS)
        g_ys[((size_t)seg * NC + c) * BINS + tid] = sbins[tid] * sinv[tid];
}

// ---------------- fcA: block-per-row, full load batch up front ---------------
__global__ void k_fcA(const float* __restrict__ W, const float* __restrict__ b) {
    const int row = blockIdx.x;                 // 0..12287
    const int seg = row >> 11;
    const int tid = threadIdx.x;
    const int lane = tid & 31, wid = tid >> 5;

    const float4* __restrict__ W4 = (const float4*)(W + (size_t)row * 8192);
    const float4* __restrict__ x4 = (const float4*)(g_ys + (size_t)seg * 8192);

    float4 w0 = W4[0 * 256 + tid];
    float4 w1 = W4[1 * 256 + tid];
    float4 w2 = W4[2 * 256 + tid];
    float4 w3 = W4[3 * 256 + tid];
    float4 w4 = W4[4 * 256 + tid];
    float4 w5 = W4[5 * 256 + tid];
    float4 w6 = W4[6 * 256 + tid];
    float4 w7 = W4[7 * 256 + tid];

    float acc0 = 0.f, acc1 = 0.f;
    {
        float4 v;
        v = x4[0 * 256 + tid]; acc0 += w0.x*v.x + w0.y*v.y + w0.z*v.z + w0.w*v.w;
        v = x4[1 * 256 + tid]; acc1 += w1.x*v.x + w1.y*v.y + w1.z*v.z + w1.w*v.w;
        v = x4[2 * 256 + tid]; acc0 += w2.x*v.x + w2.y*v.y + w2.z*v.z + w2.w*v.w;
        v = x4[3 * 256 + tid]; acc1 += w3.x*v.x + w3.y*v.y + w3.z*v.z + w3.w*v.w;
        v = x4[4 * 256 + tid]; acc0 += w4.x*v.x + w4.y*v.y + w4.z*v.z + w4.w*v.w;
        v = x4[5 * 256 + tid]; acc1 += w5.x*v.x + w5.y*v.y + w5.z*v.z + w5.w*v.w;
        v = x4[6 * 256 + tid]; acc0 += w6.x*v.x + w6.y*v.y + w6.z*v.z + w6.w*v.w;
        v = x4[7 * 256 + tid]; acc1 += w7.x*v.x + w7.y*v.y + w7.z*v.z + w7.w*v.w;
    }
    float acc = acc0 + acc1;
    #pragma unroll
    for (int off = 16; off; off >>= 1) acc += __shfl_down_sync(0xffffffffu, acc, off);

    __shared__ float ssum[8];
    if (lane == 0) ssum[wid] = acc;
    __syncthreads();
    if (tid == 0) {
        float s = ssum[0] + ssum[1] + ssum[2] + ssum[3]
                + ssum[4] + ssum[5] + ssum[6] + ssum[7];
        g_wA[row] = s + b[row];
    }
}

// ---------------- fcB: block-per-row (same pattern, 2048 wide) ---------------
__global__ void k_fcB(const float* __restrict__ W, const float* __restrict__ b) {
    const int row = blockIdx.x;                 // 0..3071
    const int seg = row >> 9;
    const int tid = threadIdx.x;
    const int lane = tid & 31, wid = tid >> 5;

    const float4* __restrict__ W4 = (const float4*)(W + (size_t)row * 2048);
    const float4* __restrict__ x4 = (const float4*)(g_wA + (size_t)seg * 2048);

    float4 w0 = W4[tid];
    float4 w1 = W4[256 + tid];
    float4 v0 = x4[tid];
    float4 v1 = x4[256 + tid];
    float acc = w0.x*v0.x + w0.y*v0.y + w0.z*v0.z + w0.w*v0.w
              + w1.x*v1.x + w1.y*v1.y + w1.z*v1.z + w1.w*v1.w;

    #pragma unroll
    for (int off = 16; off; off >>= 1) acc += __shfl_down_sync(0xffffffffu, acc, off);
    __shared__ float ssum[8];
    if (lane == 0) ssum[wid] = acc;
    __syncthreads();
    if (tid == 0) {
        float s = ssum[0] + ssum[1] + ssum[2] + ssum[3]
                + ssum[4] + ssum[5] + ssum[6] + ssum[7];
        g_wB[row] = s + b[row];
    }
}

// ---------------- generic GEMV (warp per row) for fcC ------------------------
template <int NDIM>
__global__ void k_gemv(const float* __restrict__ W, const float* __restrict__ xin,
                       const float* __restrict__ b, float* __restrict__ y,
                       int rows_per_seg, int x_seg_stride, int y_seg_stride) {
    const int gwarp = (blockIdx.x * blockDim.x + threadIdx.x) >> 5;
    const int lane  = threadIdx.x & 31;
    const int row   = gwarp;
    const int seg   = row / rows_per_seg;
    const int m     = row - seg * rows_per_seg;

    const float4* W4 = (const float4*)(W + (size_t)row * NDIM);
    const float4* x4 = (const float4*)(xin + (size_t)seg * x_seg_stride);

    float acc = 0.0f;
    #pragma unroll 4
    for (int i = lane; i < NDIM / 4; i += 32) {
        float4 w = W4[i];
        float4 v = x4[i];
        acc += w.x * v.x + w.y * v.y + w.z * v.z + w.w * v.w;
    }
    #pragma unroll
    for (int off = 16; off; off >>= 1) acc += __shfl_down_sync(0xffffffffu, acc, off);
    if (lane == 0) y[(size_t)seg * y_seg_stride + m] = acc + b[row];
}

// ---------------- final cascade ----------------------------------------------
__global__ void k_final(const float* __restrict__ p1w, const float* __restrict__ p1b,
                        const float* __restrict__ p2w, const float* __restrict__ p2b,
                        const float* __restrict__ p3w, const float* __restrict__ p3b,
                        float* __restrict__ out) {
    const int seg = blockIdx.x;
    const int tid = threadIdx.x, lane = tid & 31, wid = tid >> 5; // 8 warps
    __shared__ float w0s[512], w1s[256], w2s[128];
    float* o = out + seg * 960;

    for (int i = tid; i < 512; i += 256) w0s[i] = o[i];
    __syncthreads();

    for (int m = wid; m < 256; m += 8) {
        float acc = 0.0f;
        for (int n = lane; n < 512; n += 32) acc += p1w[m * 512 + n] * w0s[n];
        #pragma unroll
        for (int off = 16; off; off >>= 1) acc += __shfl_down_sync(0xffffffffu, acc, off);
        if (lane == 0) { float v = acc + p1b[m]; w1s[m] = v; o[512 + m] = v; }
    }
    __syncthreads();

    for (int m = wid; m < 128; m += 8) {
        float acc = 0.0f;
        for (int n = lane; n < 256; n += 32) acc += p2w[m * 256 + n] * w1s[n];
        #pragma unroll
        for (int off = 16; off; off >>= 1) acc += __shfl_down_sync(0xffffffffu, acc, off);
        if (lane == 0) { float v = acc + p2b[m]; w2s[m] = v; o[768 + m] = v; }
    }
    __syncthreads();

    for (int m = wid; m < 64; m += 8) {
        float acc = 0.0f;
        for (int n = lane; n < 128; n += 32) acc += p3w[m * 128 + n] * w2s[n];
        #pragma unroll
        for (int off = 16; off; off >>= 1) acc += __shfl_down_sync(0xffffffffu, acc, off);
        if (lane == 0) o[896 + m] = acc + p3b[m];
    }
}

// ---------------- launch ------------------------------------------------------
extern "C" void kernel_launch(void* const* d_in, const int* in_sizes, int n_in,
                              void* d_out, int out_size) {
    const float* xs      = (const float*)d_in[0];
    const int*   parsing = (const int*)  d_in[1];
    const float* fcA_w   = (const float*)d_in[2];
    const float* fcA_b   = (const float*)d_in[3];
    const float* fcB_w   = (const float*)d_in[4];
    const float* fcB_b   = (const float*)d_in[5];
    const float* fcC_w   = (const float*)d_in[6];
    const float* fcC_b   = (const float*)d_in[7];
    const float* p1_w    = (const float*)d_in[8];
    const float* p1_b    = (const float*)d_in[9];
    const float* p2_w    = (const float*)d_in[10];
    const float* p2_b    = (const float*)d_in[11];
    const float* p3_w    = (const float*)d_in[12];
    const float* p3_b    = (const float*)d_in[13];
    float* out = (float*)d_out;                     // [6,1,960]

    float* wBp; cudaGetSymbolAddress((void**)&wBp, g_wB);

    // 0,1) nops — shift the fixed ncu capture slot (4th launch) onto k_pool
    k_nop<<<1, 32>>>();
    k_nop<<<1, 32>>>();

    // 2) mask bits + scan + bin intervals
    k_scan<<<NSEG, 256>>>(parsing);

    // 3) branch-free masked segment pooling (201 MB)
    k_pool<<<dim3(NC, NSEG), 256>>>(xs);

    // 4) fcA: block-per-row (402 MB)
    k_fcA<<<NSEG * 2048, 256>>>(fcA_w, fcA_b);

    // 5) fcB: block-per-row (25 MB)
    k_fcB<<<NSEG * 512, 256>>>(fcB_w, fcB_b);

    // 6) fcC: 6x[512x512] -> out[seg*960 + 0..511] (w0)
    k_gemv<512><<<(NSEG * 512) / 8, 256>>>(fcC_w, wBp, fcC_b, out, 512, 512, 960);

    // 7) p1/p2/p3 cascade -> out[seg*960 + 512..959]
    k_final<<<NSEG, 256>>>(p1_w, p1_b, p2_w, p2_b, p3_w, p3_b, out);
}